// round 11
// baseline (speedup 1.0000x reference)
#include <cuda_runtime.h>
#include <math.h>

#define BB 8
#define NQ 900
#define DD 256
#define HH 8
#define HD 32
#define PP 4
#define BEV 200
#define FFN_D 512
#define M_ROWS (BB*NQ)   // 7200

// ---------------- consolidated scratch arena (no allocation) ----------------
#define OFF_QIN   0
#define OFF_QKV   (OFF_QIN  + M_ROWS*DD)
#define OFF_ATTN  (OFF_QKV  + M_ROWS*3*DD)
#define OFF_Q1    (OFF_ATTN + M_ROWS*DD)
#define OFF_Q2    (OFF_Q1   + M_ROWS*DD)
#define OFF_OFFS  (OFF_Q2   + M_ROWS*DD)
#define OFF_WT    (OFF_OFFS + M_ROWS*HH*PP*2)
#define OFF_FUS   (OFF_WT   + M_ROWS*HH*PP)
#define OFF_QU2   (OFF_FUS  + M_ROWS*DD)
#define OFF_Q3    (OFF_QU2  + M_ROWS*DD)
#define OFF_H1    (OFF_Q3   + M_ROWS*DD)
#define SCRATCH_TOTAL (OFF_H1 + M_ROWS*FFN_D)

__device__ float g_scratch[SCRATCH_TOTAL];

// ---------------- LayerNorm (optionally + pos) ----------------
__global__ void ln_kernel(const float* __restrict__ x, const float* __restrict__ pos,
                          const float* __restrict__ gam, const float* __restrict__ bet,
                          float* __restrict__ out)
{
    __shared__ float sb[8];
    __shared__ float stat;
    int r = blockIdx.x, t = threadIdx.x;
    int lane = t & 31, w = t >> 5;
    float v = x[r*DD + t];
    if (pos) v += pos[r*DD + t];

    float s = v;
    #pragma unroll
    for (int o = 16; o; o >>= 1) s += __shfl_xor_sync(0xffffffffu, s, o);
    if (lane == 0) sb[w] = s;
    __syncthreads();
    if (t == 0) { float tot = 0.f; for (int i = 0; i < 8; i++) tot += sb[i]; stat = tot * (1.0f/DD); }
    __syncthreads();
    float mean = stat;
    float c = v - mean;
    __syncthreads();
    s = c * c;
    #pragma unroll
    for (int o = 16; o; o >>= 1) s += __shfl_xor_sync(0xffffffffu, s, o);
    if (lane == 0) sb[w] = s;
    __syncthreads();
    if (t == 0) { float tot = 0.f; for (int i = 0; i < 8; i++) tot += sb[i]; stat = rsqrtf(tot * (1.0f/DD) + 1e-5f); }
    __syncthreads();
    out[r*DD + t] = c * stat * gam[t] + bet[t];
}

// ---------------- GEMM: C = A[M,K] * B[N,K]^T + bias (+res) (+act) ----------------
// 128x64 tile, BK=32 (L2-latency-covering prefetch), double-buffered dyn smem.
// act: 0 none, 1 relu, 2 tanh*scale
// dyn smem floats: As[2][32][136] @0 (4352/buf), Bs[2][32][72] @8704 (2304/buf)
#define GEMM_SMEM_BYTES ((2*32*136 + 2*32*72)*4)   // 53248 B

__global__ __launch_bounds__(256, 2)
void gemm_nt(const float* __restrict__ A, const float* __restrict__ Bw,
             const float* __restrict__ bias, const float* __restrict__ res,
             float* __restrict__ C, int M, int N, int K, int act, float scale)
{
    extern __shared__ float gsm[];
    float* AsBuf[2] = { gsm, gsm + 4352 };
    float* BsBuf[2] = { gsm + 8704, gsm + 8704 + 2304 };

    int bm = blockIdx.y * 128, bn = blockIdx.x * 64;
    int tid = threadIdx.x;
    int tx = tid & 15, ty = tid >> 4;

    // load roles: A 128 rows x 32 k -> 16 floats/thread; B 64 x 32 -> 8 floats/thread
    int am = tid >> 1, ak = (tid & 1) * 16;
    int bnr = tid >> 2, bk = (tid & 3) * 8;
    int gmA = bm + am;  bool va = (gmA < M);
    int gnB = bn + bnr; bool vb = (gnB < N);
    const float* Ap = A  + (size_t)(va ? gmA : 0) * K + ak;
    const float* Bp = Bw + (size_t)(vb ? gnB : 0) * K + bk;

    const float4 fz = make_float4(0.f, 0.f, 0.f, 0.f);
    float4 ra[4], rb[2];
    #pragma unroll
    for (int l = 0; l < 4; l++) ra[l] = va ? *(const float4*)(Ap + l*4) : fz;
    #pragma unroll
    for (int l = 0; l < 2; l++) rb[l] = vb ? *(const float4*)(Bp + l*4) : fz;

    float acc[8][4];
    #pragma unroll
    for (int i = 0; i < 8; i++)
        #pragma unroll
        for (int j = 0; j < 4; j++) acc[i][j] = 0.f;

    // prime buffer 0
    {
        float* Ad = AsBuf[0];
        float* Bd = BsBuf[0];
        #pragma unroll
        for (int l = 0; l < 4; l++) {
            Ad[(ak + 4*l + 0)*136 + am] = ra[l].x;
            Ad[(ak + 4*l + 1)*136 + am] = ra[l].y;
            Ad[(ak + 4*l + 2)*136 + am] = ra[l].z;
            Ad[(ak + 4*l + 3)*136 + am] = ra[l].w;
        }
        #pragma unroll
        for (int l = 0; l < 2; l++) {
            Bd[(bk + 4*l + 0)*72 + bnr] = rb[l].x;
            Bd[(bk + 4*l + 1)*72 + bnr] = rb[l].y;
            Bd[(bk + 4*l + 2)*72 + bnr] = rb[l].z;
            Bd[(bk + 4*l + 3)*72 + bnr] = rb[l].w;
        }
    }
    __syncthreads();

    int nt = K >> 5;
    for (int t = 0; t < nt; t++) {
        int buf = t & 1;
        const float* Ac = AsBuf[buf];
        const float* Bc = BsBuf[buf];
        bool more = (t + 1 < nt);
        if (more) {
            const float* Ap2 = Ap + (t + 1) * 32;
            const float* Bp2 = Bp + (t + 1) * 32;
            #pragma unroll
            for (int l = 0; l < 4; l++) ra[l] = va ? *(const float4*)(Ap2 + l*4) : fz;
            #pragma unroll
            for (int l = 0; l < 2; l++) rb[l] = vb ? *(const float4*)(Bp2 + l*4) : fz;
        }
        #pragma unroll
        for (int kk = 0; kk < 32; kk++) {
            float4 x0 = *(const float4*)(Ac + kk*136 + ty*8);
            float4 x1 = *(const float4*)(Ac + kk*136 + ty*8 + 4);
            float4 y0 = *(const float4*)(Bc + kk*72 + tx*4);
            float av[8] = {x0.x,x0.y,x0.z,x0.w,x1.x,x1.y,x1.z,x1.w};
            float bv[4] = {y0.x,y0.y,y0.z,y0.w};
            #pragma unroll
            for (int i = 0; i < 8; i++)
                #pragma unroll
                for (int j = 0; j < 4; j++)
                    acc[i][j] += av[i] * bv[j];
        }
        if (more) {
            float* Ad = AsBuf[buf ^ 1];
            float* Bd = BsBuf[buf ^ 1];
            #pragma unroll
            for (int l = 0; l < 4; l++) {
                Ad[(ak + 4*l + 0)*136 + am] = ra[l].x;
                Ad[(ak + 4*l + 1)*136 + am] = ra[l].y;
                Ad[(ak + 4*l + 2)*136 + am] = ra[l].z;
                Ad[(ak + 4*l + 3)*136 + am] = ra[l].w;
            }
            #pragma unroll
            for (int l = 0; l < 2; l++) {
                Bd[(bk + 4*l + 0)*72 + bnr] = rb[l].x;
                Bd[(bk + 4*l + 1)*72 + bnr] = rb[l].y;
                Bd[(bk + 4*l + 2)*72 + bnr] = rb[l].z;
                Bd[(bk + 4*l + 3)*72 + bnr] = rb[l].w;
            }
        }
        __syncthreads();
    }

    // epilogue
    bool vecN = (bn + 64 <= N);
    #pragma unroll
    for (int i = 0; i < 8; i++) {
        int gm = bm + ty*8 + i;
        if (gm >= M) continue;
        int gn0 = bn + tx*4;
        if (vecN) {
            float4 bia = *(const float4*)(bias + gn0);
            float4 v = make_float4(acc[i][0] + bia.x, acc[i][1] + bia.y,
                                   acc[i][2] + bia.z, acc[i][3] + bia.w);
            if (act == 1) {
                v.x = fmaxf(v.x, 0.f); v.y = fmaxf(v.y, 0.f);
                v.z = fmaxf(v.z, 0.f); v.w = fmaxf(v.w, 0.f);
            } else if (act == 2) {
                v.x = tanhf(v.x)*scale; v.y = tanhf(v.y)*scale;
                v.z = tanhf(v.z)*scale; v.w = tanhf(v.w)*scale;
            }
            if (res) {
                float4 r = *(const float4*)(res + (size_t)gm*N + gn0);
                v.x += r.x; v.y += r.y; v.z += r.z; v.w += r.w;
            }
            *(float4*)(C + (size_t)gm*N + gn0) = v;
        } else {
            #pragma unroll
            for (int j = 0; j < 4; j++) {
                int gn = gn0 + j;
                if (gn >= N) continue;
                float v = acc[i][j] + bias[gn];
                if (act == 1) v = fmaxf(v, 0.f);
                else if (act == 2) v = tanhf(v) * scale;
                if (res) v += res[(size_t)gm * N + gn];
                C[(size_t)gm * N + gn] = v;
            }
        }
    }
}

// ---------------- Flash-style multi-head self-attention ----------------
// grid (15, 8, 8), block 256. q-tile 64, k-chunk 128, online softmax.
// dyn smem (floats): Qs[32][68]@0; Ks[32][132]@2176; Ps(128r,str100,swz)@6400;
// Lsm[64]@19200; Vs[128][32] swizzled @19264. total 23360 f = 93440 B.
#define ATT_SMEM_BYTES (23360*4)

__global__ __launch_bounds__(256, 2)
void attn_kernel(const float* __restrict__ qkv, float* __restrict__ out)
{
    extern __shared__ float sm[];
    float* Qs  = sm;            // [d][q] : 32 x 68
    float* Ks  = sm + 2176;     // [d][k] : 32 x 132
    float* Ps  = sm + 6400;     // [k][q] swizzled, stride 100
    float* Lsm = sm + 19200;    // [64]
    float* Vs  = sm + 19264;    // [k][d] swizzled: col slot ((d>>2)+k)&7

    int b = blockIdx.z, h = blockIdx.y;
    int q0 = blockIdx.x * 64;
    int tid = threadIdx.x;
    int tx = tid & 31, ty = tid >> 5;
    const float SCALE = 0.17677669529663687f;
    const float4 fz = make_float4(0,0,0,0);

    // ---- load Q tile -> Qs[d][q] (transposed) ----
    {
        int q = tid >> 2, dg = tid & 3;
        int gq = q0 + q;
        const float* src = qkv + (size_t)(b*NQ + (gq < NQ ? gq : 0))*768 + h*32 + dg*8;
        float4 x0 = fz, x1 = fz;
        if (gq < NQ) { x0 = *(const float4*)src; x1 = *(const float4*)(src + 4); }
        int d = dg * 8;
        Qs[(d+0)*68 + q] = x0.x; Qs[(d+1)*68 + q] = x0.y;
        Qs[(d+2)*68 + q] = x0.z; Qs[(d+3)*68 + q] = x0.w;
        Qs[(d+4)*68 + q] = x1.x; Qs[(d+5)*68 + q] = x1.y;
        Qs[(d+6)*68 + q] = x1.z; Qs[(d+7)*68 + q] = x1.w;
    }

    float o[8][4];
    float m[8], l[8];
    #pragma unroll
    for (int i = 0; i < 8; i++) {
        m[i] = -1e30f; l[i] = 0.f;
        #pragma unroll
        for (int j = 0; j < 4; j++) o[i][j] = 0.f;
    }

    int kg = tx >> 3, dgi = tx & 7;   // O-phase roles: k group / d group

    for (int c = 0; c < 8; c++) {
        int kc0 = c * 128;

        // ---- load K chunk -> Ks[d][k] (transposed) ----
        {
            int k = tid >> 1, dg = tid & 1;
            int kglob = kc0 + k;
            const float* src = qkv + (size_t)(b*NQ + (kglob < NQ ? kglob : 0))*768 + 256 + h*32 + dg*16;
            float4 x0 = fz, x1 = fz, x2 = fz, x3 = fz;
            if (kglob < NQ) {
                x0 = *(const float4*)(src);      x1 = *(const float4*)(src + 4);
                x2 = *(const float4*)(src + 8);  x3 = *(const float4*)(src + 12);
            }
            int d = dg * 16;
            Ks[(d+ 0)*132 + k] = x0.x; Ks[(d+ 1)*132 + k] = x0.y;
            Ks[(d+ 2)*132 + k] = x0.z; Ks[(d+ 3)*132 + k] = x0.w;
            Ks[(d+ 4)*132 + k] = x1.x; Ks[(d+ 5)*132 + k] = x1.y;
            Ks[(d+ 6)*132 + k] = x1.z; Ks[(d+ 7)*132 + k] = x1.w;
            Ks[(d+ 8)*132 + k] = x2.x; Ks[(d+ 9)*132 + k] = x2.y;
            Ks[(d+10)*132 + k] = x2.z; Ks[(d+11)*132 + k] = x2.w;
            Ks[(d+12)*132 + k] = x3.x; Ks[(d+13)*132 + k] = x3.y;
            Ks[(d+14)*132 + k] = x3.z; Ks[(d+15)*132 + k] = x3.w;
        }
        // ---- load V chunk -> Vs[k][d] swizzled ----
        {
            int k = tid >> 1, dv = (tid & 1) * 16;
            int kglob = kc0 + k;
            const float* src = qkv + (size_t)(b*NQ + (kglob < NQ ? kglob : 0))*768 + 512 + h*32 + dv;
            float4 v0 = fz, v1 = fz, v2 = fz, v3 = fz;
            if (kglob < NQ) {
                v0 = *(const float4*)(src);      v1 = *(const float4*)(src + 4);
                v2 = *(const float4*)(src + 8);  v3 = *(const float4*)(src + 12);
            }
            int dq = dv >> 2;   // 0 or 4
            *(float4*)(Vs + k*32 + (((dq + 0) + k) & 7)*4) = v0;
            *(float4*)(Vs + k*32 + (((dq + 1) + k) & 7)*4) = v1;
            *(float4*)(Vs + k*32 + (((dq + 2) + k) & 7)*4) = v2;
            *(float4*)(Vs + k*32 + (((dq + 3) + k) & 7)*4) = v3;
        }
        __syncthreads();   // Ks,Vs ready

        // ---- S = Q K^T  (thread tile: 8 q x 4 k) ----
        float acc[8][4];
        #pragma unroll
        for (int i = 0; i < 8; i++)
            #pragma unroll
            for (int j = 0; j < 4; j++) acc[i][j] = 0.f;

        #pragma unroll 8
        for (int d = 0; d < 32; d++) {
            const float4* Q4 = (const float4*)(Qs + d*68);
            float4 qa = Q4[ty*2], qb = Q4[ty*2 + 1];
            float4 kv = ((const float4*)(Ks + d*132))[tx];
            float qq[8] = {qa.x,qa.y,qa.z,qa.w,qb.x,qb.y,qb.z,qb.w};
            #pragma unroll
            for (int i = 0; i < 8; i++) {
                acc[i][0] += qq[i] * kv.x;
                acc[i][1] += qq[i] * kv.y;
                acc[i][2] += qq[i] * kv.z;
                acc[i][3] += qq[i] * kv.w;
            }
        }

        // scale + mask
        #pragma unroll
        for (int j = 0; j < 4; j++) {
            bool vk = (kc0 + tx*4 + j) < NQ;
            #pragma unroll
            for (int i = 0; i < 8; i++)
                acc[i][j] = vk ? acc[i][j]*SCALE : -1e30f;
        }

        // online softmax per q row
        #pragma unroll
        for (int i = 0; i < 8; i++) {
            float rm = fmaxf(fmaxf(acc[i][0], acc[i][1]), fmaxf(acc[i][2], acc[i][3]));
            #pragma unroll
            for (int off = 16; off; off >>= 1) rm = fmaxf(rm, __shfl_xor_sync(0xffffffffu, rm, off));
            float mn = fmaxf(m[i], rm);
            float alpha = __expf(m[i] - mn);
            m[i] = mn;
            float ls = 0.f;
            #pragma unroll
            for (int j = 0; j < 4; j++) {
                float p = __expf(acc[i][j] - mn);
                acc[i][j] = p;
                ls += p;
            }
            #pragma unroll
            for (int off = 16; off; off >>= 1) ls += __shfl_xor_sync(0xffffffffu, ls, off);
            l[i] = l[i]*alpha + ls;
            #pragma unroll
            for (int j = 0; j < 4; j++) o[i][j] *= alpha;
        }

        // store P -> Ps[k][q] (stride 100, swizzle ((k>>2)&7)*4)
        {
            int sw = (tx & 7) * 4;
            #pragma unroll
            for (int j = 0; j < 4; j++) {
                float* dst = Ps + (tx*4 + j)*100 + sw + ty*8;
                *(float4*)(dst)     = make_float4(acc[0][j], acc[1][j], acc[2][j], acc[3][j]);
                *(float4*)(dst + 4) = make_float4(acc[4][j], acc[5][j], acc[6][j], acc[7][j]);
            }
        }
        __syncthreads();   // Ps ready

        // ---- O += P V  (thread: 8 q x 4 d, k split 4-way over kg) ----
        {
            #pragma unroll 8
            for (int i2 = 0; i2 < 32; i2++) {
                int k = 4*i2 + kg;
                const float* prow = Ps + k*100 + (i2 & 7)*4;
                float4 pa = *(const float4*)(prow + ty*8);
                float4 pb = *(const float4*)(prow + ty*8 + 4);
                float4 v = *(const float4*)(Vs + k*32 + ((dgi + k) & 7)*4);
                float pv[8] = {pa.x,pa.y,pa.z,pa.w,pb.x,pb.y,pb.z,pb.w};
                #pragma unroll
                for (int i = 0; i < 8; i++) {
                    o[i][0] += pv[i] * v.x;
                    o[i][1] += pv[i] * v.y;
                    o[i][2] += pv[i] * v.z;
                    o[i][3] += pv[i] * v.w;
                }
            }
        }
        __syncthreads();   // protect Ps/Vs before next chunk's stores
    }

    // ---- reduce 4 kg partials via smem (reuse Ps area) ----
    float* red = Ps;
    #pragma unroll
    for (int i = 0; i < 8; i++) {
        float* dst = red + kg*2048 + (ty*8 + i)*32 + dgi*4;
        *(float4*)dst = make_float4(o[i][0], o[i][1], o[i][2], o[i][3]);
    }
    if (tx == 0) {
        #pragma unroll
        for (int i = 0; i < 8; i++) Lsm[ty*8 + i] = l[i];
    }
    __syncthreads();

    {
        int q = tid >> 2, dgrp = tid & 3;
        int gq = q0 + q;
        if (gq < NQ) {
            int d = dgrp * 8;
            float s0 = 0, s1 = 0, s2 = 0, s3 = 0, s4 = 0, s5 = 0, s6 = 0, s7 = 0;
            #pragma unroll
            for (int g = 0; g < 4; g++) {
                const float* src = red + g*2048 + q*32 + d;
                float4 u = *(const float4*)(src);
                float4 w = *(const float4*)(src + 4);
                s0 += u.x; s1 += u.y; s2 += u.z; s3 += u.w;
                s4 += w.x; s5 += w.y; s6 += w.z; s7 += w.w;
            }
            float linv = 1.f / Lsm[q];
            float* dst = out + (size_t)(b*NQ + gq)*DD + h*32 + d;
            *(float4*)(dst)     = make_float4(s0*linv, s1*linv, s2*linv, s3*linv);
            *(float4*)(dst + 4) = make_float4(s4*linv, s5*linv, s6*linv, s7*linv);
        }
    }
}

// ---------------- BEV bilinear sampling + inline weight softmax + fuse ----------------
__global__ void sample_kernel(const float* __restrict__ mem, const float* __restrict__ ref,
                              const float* __restrict__ off, const float* __restrict__ wt,
                              float* __restrict__ out)
{
    int idx = blockIdx.x * 256 + threadIdx.x;
    if (idx >= M_ROWS * DD) return;
    int c = idx & 31;
    int h = (idx >> 5) & 7;
    int row = idx >> 8;            // b*NQ + q
    int b = row / NQ;

    float rx = ref[row*2 + 0], ry = ref[row*2 + 1];
    const float* offr = off + (size_t)row*64 + h*8;
    const float* wtr  = wt  + (size_t)row*32 + h*4;
    const float* memb = mem + (size_t)b * (BEV*BEV) * DD + h*HD + c;

    // inline softmax over P=4
    float w0 = wtr[0], w1 = wtr[1], w2 = wtr[2], w3 = wtr[3];
    float wm = fmaxf(fmaxf(w0, w1), fmaxf(w2, w3));
    float e0 = __expf(w0 - wm), e1 = __expf(w1 - wm), e2 = __expf(w2 - wm), e3 = __expf(w3 - wm);
    float winv = 1.f / (e0 + e1 + e2 + e3);
    float wsm[4] = {e0*winv, e1*winv, e2*winv, e3*winv};

    float acc = 0.f;
    #pragma unroll
    for (int p = 0; p < PP; p++) {
        float gx = (rx + offr[p*2 + 0]) * (float)BEV - 0.5f;
        float gy = (ry + offr[p*2 + 1]) * (float)BEV - 0.5f;
        float x0f = floorf(gx), y0f = floorf(gy);
        int x0 = (int)x0f, y0 = (int)y0f;
        float wx1 = gx - x0f, wy1 = gy - y0f;
        float wx0 = 1.f - wx1, wy0 = 1.f - wy1;
        float v = 0.f;
        if ((unsigned)x0     < BEV && (unsigned)y0     < BEV) v += wx0*wy0 * memb[(size_t)(y0*BEV + x0    )*DD];
        if ((unsigned)(x0+1) < BEV && (unsigned)y0     < BEV) v += wx1*wy0 * memb[(size_t)(y0*BEV + x0 + 1)*DD];
        if ((unsigned)x0     < BEV && (unsigned)(y0+1) < BEV) v += wx0*wy1 * memb[(size_t)((y0+1)*BEV + x0    )*DD];
        if ((unsigned)(x0+1) < BEV && (unsigned)(y0+1) < BEV) v += wx1*wy1 * memb[(size_t)((y0+1)*BEV + x0 + 1)*DD];
        acc += wsm[p] * v;
    }
    out[idx] = acc;
}

// ---------------- launch ----------------
extern "C" void kernel_launch(void* const* d_in, const int* in_sizes, int n_in,
                              void* d_out, int out_size)
{
    const float* query   = (const float*)d_in[0];
    const float* memory  = (const float*)d_in[1];
    const float* refpts  = (const float*)d_in[2];
    const float* qpos    = (const float*)d_in[3];
    const float* in_w    = (const float*)d_in[4];
    const float* in_b    = (const float*)d_in[5];
    const float* out_w   = (const float*)d_in[6];
    const float* out_b   = (const float*)d_in[7];
    const float* off_w   = (const float*)d_in[8];
    const float* off_b   = (const float*)d_in[9];
    const float* wt_w    = (const float*)d_in[10];
    const float* wt_b    = (const float*)d_in[11];
    const float* co_w    = (const float*)d_in[12];
    const float* co_b    = (const float*)d_in[13];
    const float* f_w1    = (const float*)d_in[14];
    const float* f_b1    = (const float*)d_in[15];
    const float* f_w2    = (const float*)d_in[16];
    const float* f_b2    = (const float*)d_in[17];
    const float* n1s     = (const float*)d_in[18];
    const float* n1b     = (const float*)d_in[19];
    const float* n2s     = (const float*)d_in[20];
    const float* n2b     = (const float*)d_in[21];
    const float* n3s     = (const float*)d_in[22];
    const float* n3b     = (const float*)d_in[23];

    float* base = nullptr;
    cudaGetSymbolAddress((void**)&base, g_scratch);
    float* qin  = base + OFF_QIN;
    float* qkv  = base + OFF_QKV;
    float* attn = base + OFF_ATTN;
    float* q1   = base + OFF_Q1;
    float* q2   = base + OFF_Q2;
    float* off  = base + OFF_OFFS;
    float* wt   = base + OFF_WT;
    float* fus  = base + OFF_FUS;
    float* qu2  = base + OFF_QU2;
    float* q3   = base + OFF_Q3;
    float* h1   = base + OFF_H1;

    cudaFuncSetAttribute(attn_kernel, cudaFuncAttributeMaxDynamicSharedMemorySize, ATT_SMEM_BYTES);
    cudaFuncSetAttribute(gemm_nt, cudaFuncAttributeMaxDynamicSharedMemorySize, GEMM_SMEM_BYTES);

    const int GY = (M_ROWS + 127) / 128;   // 57

    // 1) q_in = LN(query + pos; n1)
    ln_kernel<<<M_ROWS, 256>>>(query, qpos, n1s, n1b, qin);
    // 2) qkv = q_in @ in_w^T + in_b
    gemm_nt<<<dim3(12, GY), 256, GEMM_SMEM_BYTES>>>(qin, in_w, in_b, nullptr, qkv, M_ROWS, 768, 256, 0, 0.f);
    // 3) self-attention (flash)
    attn_kernel<<<dim3((NQ + 63) / 64, HH, BB), 256, ATT_SMEM_BYTES>>>(qkv, attn);
    // 4) query1 = query + attn @ out_w^T + out_b
    gemm_nt<<<dim3(4, GY), 256, GEMM_SMEM_BYTES>>>(attn, out_w, out_b, query, q1, M_ROWS, 256, 256, 0, 0.f);
    // 5) q2 = LN(query1 + pos; n2)
    ln_kernel<<<M_ROWS, 256>>>(q1, qpos, n2s, n2b, q2);
    // 6) offsets = tanh(q2 @ off_w^T + off_b) * RADIUS
    gemm_nt<<<dim3(1, GY), 256, GEMM_SMEM_BYTES>>>(q2, off_w, off_b, nullptr, off, M_ROWS, 64, 256, 2, 0.2f);
    // 7) raw weights (softmax fused into sample_kernel)
    gemm_nt<<<dim3(1, GY), 256, GEMM_SMEM_BYTES>>>(q2, wt_w, wt_b, nullptr, wt, M_ROWS, 32, 256, 0, 0.f);
    // 8) bilinear sample + softmax + fuse
    sample_kernel<<<(M_ROWS * DD + 255) / 256, 256>>>(memory, refpts, off, wt, fus);
    // 9) query2 = query1 + fused @ co_w^T + co_b
    gemm_nt<<<dim3(4, GY), 256, GEMM_SMEM_BYTES>>>(fus, co_w, co_b, q1, qu2, M_ROWS, 256, 256, 0, 0.f);
    // 10) q3 = LN(query2; n3)
    ln_kernel<<<M_ROWS, 256>>>(qu2, nullptr, n3s, n3b, q3);
    // 11) h1 = relu(q3 @ f_w1^T + f_b1)
    gemm_nt<<<dim3(8, GY), 256, GEMM_SMEM_BYTES>>>(q3, f_w1, f_b1, nullptr, h1, M_ROWS, 512, 256, 1, 0.f);
    // 12) out = query2 + h1 @ f_w2^T + f_b2
    gemm_nt<<<dim3(4, GY), 256, GEMM_SMEM_BYTES>>>(h1, f_w2, f_b2, qu2, (float*)d_out, M_ROWS, 256, 512, 0, 0.f);
}

// round 13
// speedup vs baseline: 1.2929x; 1.2929x over previous
#include <cuda_runtime.h>
#include <cuda_bf16.h>
#include <math.h>

#define BB 8
#define NQ 900
#define DD 256
#define HH 8
#define HD 32
#define PP 4
#define BEV 200
#define FFN_D 512
#define M_ROWS (BB*NQ)   // 7200

// ---------------- consolidated scratch arena (no allocation) ----------------
#define OFF_QIN   0
#define OFF_QKV   (OFF_QIN  + M_ROWS*DD)
#define OFF_ATTN  (OFF_QKV  + M_ROWS*3*DD)
#define OFF_Q1    (OFF_ATTN + M_ROWS*DD)
#define OFF_Q2    (OFF_Q1   + M_ROWS*DD)
#define OFF_OFFS  (OFF_Q2   + M_ROWS*DD)
#define OFF_WT    (OFF_OFFS + M_ROWS*HH*PP*2)
#define OFF_FUS   (OFF_WT   + M_ROWS*HH*PP)
#define OFF_QU2   (OFF_FUS  + M_ROWS*DD)
#define OFF_Q3    (OFF_QU2  + M_ROWS*DD)
#define OFF_H1    (OFF_Q3   + M_ROWS*DD)
#define SCRATCH_TOTAL (OFF_H1 + M_ROWS*FFN_D)

__device__ float g_scratch[SCRATCH_TOTAL];

// ---------------- LayerNorm (optionally + pos) ----------------
__global__ void ln_kernel(const float* __restrict__ x, const float* __restrict__ pos,
                          const float* __restrict__ gam, const float* __restrict__ bet,
                          float* __restrict__ out)
{
    __shared__ float sb[8];
    __shared__ float stat;
    int r = blockIdx.x, t = threadIdx.x;
    int lane = t & 31, w = t >> 5;
    float v = x[r*DD + t];
    if (pos) v += pos[r*DD + t];

    float s = v;
    #pragma unroll
    for (int o = 16; o; o >>= 1) s += __shfl_xor_sync(0xffffffffu, s, o);
    if (lane == 0) sb[w] = s;
    __syncthreads();
    if (t == 0) { float tot = 0.f; for (int i = 0; i < 8; i++) tot += sb[i]; stat = tot * (1.0f/DD); }
    __syncthreads();
    float mean = stat;
    float c = v - mean;
    __syncthreads();
    s = c * c;
    #pragma unroll
    for (int o = 16; o; o >>= 1) s += __shfl_xor_sync(0xffffffffu, s, o);
    if (lane == 0) sb[w] = s;
    __syncthreads();
    if (t == 0) { float tot = 0.f; for (int i = 0; i < 8; i++) tot += sb[i]; stat = rsqrtf(tot * (1.0f/DD) + 1e-5f); }
    __syncthreads();
    out[r*DD + t] = c * stat * gam[t] + bet[t];
}

// ---------------- Tensor-core GEMM (bf16 2-term split, 3-pass fp32 acc) ----------------
// C = A[M,K] * B[N,K]^T + bias (+res) (+relu). N must be multiple of 64, K of 16.
// Tile 128x64, BK=16, 256 threads (warp grid 4m x 2n, each warp 32x32).
__device__ __forceinline__ void cvt_pair(float x0, float x1, unsigned &hi, unsigned &lo)
{
    __nv_bfloat16 h0 = __float2bfloat16(x0);
    __nv_bfloat16 h1 = __float2bfloat16(x1);
    float l0 = x0 - __bfloat162float(h0);
    float l1 = x1 - __bfloat162float(h1);
    __nv_bfloat162 hp; hp.x = h0; hp.y = h1;
    __nv_bfloat162 lp = __floats2bfloat162_rn(l0, l1);
    hi = *reinterpret_cast<unsigned*>(&hp);
    lo = *reinterpret_cast<unsigned*>(&lp);
}

#define MMA_BF16(c, a, b) \
    asm volatile("mma.sync.aligned.m16n8k16.row.col.f32.bf16.bf16.f32 " \
        "{%0,%1,%2,%3}, {%4,%5,%6,%7}, {%8,%9}, {%0,%1,%2,%3};" \
        : "+f"((c)[0]), "+f"((c)[1]), "+f"((c)[2]), "+f"((c)[3]) \
        : "r"((a)[0]), "r"((a)[1]), "r"((a)[2]), "r"((a)[3]), "r"((b)[0]), "r"((b)[1]))

__global__ __launch_bounds__(256, 2)
void gemm_tc(const float* __restrict__ A, const float* __restrict__ Bw,
             const float* __restrict__ bias, const float* __restrict__ res,
             float* __restrict__ C, int M, int N, int K, int act)
{
    // u32 smem: pairs of bf16 along k. Row strides of 12 u32 (8 data + 4 pad)
    // give conflict-free fragment loads (12*g mod 32 distinct over g=0..7).
    __shared__ unsigned sAhi[2][128*12];
    __shared__ unsigned sAlo[2][128*12];
    __shared__ unsigned sBhi[2][64*12];
    __shared__ unsigned sBlo[2][64*12];

    int bm = blockIdx.y * 128, bn = blockIdx.x * 64;
    int tid = threadIdx.x;
    int warp = tid >> 5, lane = tid & 31;
    int wm = warp & 3, wn = warp >> 2;       // warp tile: rows wm*32, cols wn*32
    int g = lane >> 2, tig = lane & 3;

    // load roles: A row am, k-offset akk (8 floats); B row bnr, k-offset bkk (4 floats)
    int am = tid >> 1, akk = (tid & 1) * 8;
    int bnr = tid >> 2, bkk = (tid & 3) * 4;
    bool va = (bm + am) < M;
    const float* Ap = A  + (size_t)(va ? bm + am : 0) * K + akk;
    const float* Bp = Bw + (size_t)(bn + bnr) * K + bkk;

    float ra[8], rb[4];
    {
        float4 x0 = *(const float4*)(Ap), x1 = *(const float4*)(Ap + 4);
        float4 y0 = *(const float4*)(Bp);
        ra[0]=x0.x; ra[1]=x0.y; ra[2]=x0.z; ra[3]=x0.w;
        ra[4]=x1.x; ra[5]=x1.y; ra[6]=x1.z; ra[7]=x1.w;
        rb[0]=y0.x; rb[1]=y0.y; rb[2]=y0.z; rb[3]=y0.w;
    }

    float acc[2][4][4];
    #pragma unroll
    for (int i = 0; i < 2; i++)
        #pragma unroll
        for (int j = 0; j < 4; j++)
            #pragma unroll
            for (int k = 0; k < 4; k++) acc[i][j][k] = 0.f;

    // stage current registers into buffer
    {
        #pragma unroll
        for (int p = 0; p < 4; p++) {
            unsigned hi, lo;
            cvt_pair(ra[2*p], ra[2*p+1], hi, lo);
            sAhi[0][am*12 + (akk>>1) + p] = hi;
            sAlo[0][am*12 + (akk>>1) + p] = lo;
        }
        #pragma unroll
        for (int p = 0; p < 2; p++) {
            unsigned hi, lo;
            cvt_pair(rb[2*p], rb[2*p+1], hi, lo);
            sBhi[0][bnr*12 + (bkk>>1) + p] = hi;
            sBlo[0][bnr*12 + (bkk>>1) + p] = lo;
        }
    }
    __syncthreads();

    int nt = K >> 4;
    for (int t = 0; t < nt; t++) {
        int buf = t & 1;
        bool more = (t + 1 < nt);
        if (more) {
            const float* Ap2 = Ap + (t + 1) * 16;
            const float* Bp2 = Bp + (t + 1) * 16;
            float4 x0 = *(const float4*)(Ap2), x1 = *(const float4*)(Ap2 + 4);
            float4 y0 = *(const float4*)(Bp2);
            ra[0]=x0.x; ra[1]=x0.y; ra[2]=x0.z; ra[3]=x0.w;
            ra[4]=x1.x; ra[5]=x1.y; ra[6]=x1.z; ra[7]=x1.w;
            rb[0]=y0.x; rb[1]=y0.y; rb[2]=y0.z; rb[3]=y0.w;
        }

        // fragment loads
        unsigned aHi[2][4], aLo[2][4], bHi[4][2], bLo[4][2];
        #pragma unroll
        for (int mt = 0; mt < 2; mt++) {
            int r = wm*32 + mt*16 + g;
            aHi[mt][0] = sAhi[buf][ r     *12 + tig    ];
            aHi[mt][1] = sAhi[buf][(r + 8)*12 + tig    ];
            aHi[mt][2] = sAhi[buf][ r     *12 + tig + 4];
            aHi[mt][3] = sAhi[buf][(r + 8)*12 + tig + 4];
            aLo[mt][0] = sAlo[buf][ r     *12 + tig    ];
            aLo[mt][1] = sAlo[buf][(r + 8)*12 + tig    ];
            aLo[mt][2] = sAlo[buf][ r     *12 + tig + 4];
            aLo[mt][3] = sAlo[buf][(r + 8)*12 + tig + 4];
        }
        #pragma unroll
        for (int n2 = 0; n2 < 4; n2++) {
            int cn = wn*32 + n2*8 + g;
            bHi[n2][0] = sBhi[buf][cn*12 + tig    ];
            bHi[n2][1] = sBhi[buf][cn*12 + tig + 4];
            bLo[n2][0] = sBlo[buf][cn*12 + tig    ];
            bLo[n2][1] = sBlo[buf][cn*12 + tig + 4];
        }

        #pragma unroll
        for (int mt = 0; mt < 2; mt++)
            #pragma unroll
            for (int n2 = 0; n2 < 4; n2++) {
                MMA_BF16(acc[mt][n2], aHi[mt], bHi[n2]);
                MMA_BF16(acc[mt][n2], aHi[mt], bLo[n2]);
                MMA_BF16(acc[mt][n2], aLo[mt], bHi[n2]);
            }

        if (more) {
            int nb = buf ^ 1;
            #pragma unroll
            for (int p = 0; p < 4; p++) {
                unsigned hi, lo;
                cvt_pair(ra[2*p], ra[2*p+1], hi, lo);
                sAhi[nb][am*12 + (akk>>1) + p] = hi;
                sAlo[nb][am*12 + (akk>>1) + p] = lo;
            }
            #pragma unroll
            for (int p = 0; p < 2; p++) {
                unsigned hi, lo;
                cvt_pair(rb[2*p], rb[2*p+1], hi, lo);
                sBhi[nb][bnr*12 + (bkk>>1) + p] = hi;
                sBlo[nb][bnr*12 + (bkk>>1) + p] = lo;
            }
        }
        __syncthreads();
    }

    // epilogue: c0,c1 -> (row, col..col+1); c2,c3 -> (row+8, ...)
    #pragma unroll
    for (int mt = 0; mt < 2; mt++) {
        #pragma unroll
        for (int n2 = 0; n2 < 4; n2++) {
            int col = bn + wn*32 + n2*8 + tig*2;
            float2 bia = *(const float2*)(bias + col);
            int r0 = bm + wm*32 + mt*16 + g;
            int r1 = r0 + 8;
            float v0 = acc[mt][n2][0] + bia.x;
            float v1 = acc[mt][n2][1] + bia.y;
            float v2 = acc[mt][n2][2] + bia.x;
            float v3 = acc[mt][n2][3] + bia.y;
            if (act == 1) {
                v0 = fmaxf(v0, 0.f); v1 = fmaxf(v1, 0.f);
                v2 = fmaxf(v2, 0.f); v3 = fmaxf(v3, 0.f);
            }
            if (r0 < M) {
                if (res) {
                    float2 rr = *(const float2*)(res + (size_t)r0*N + col);
                    v0 += rr.x; v1 += rr.y;
                }
                *(float2*)(C + (size_t)r0*N + col) = make_float2(v0, v1);
            }
            if (r1 < M) {
                if (res) {
                    float2 rr = *(const float2*)(res + (size_t)r1*N + col);
                    v2 += rr.x; v3 += rr.y;
                }
                *(float2*)(C + (size_t)r1*N + col) = make_float2(v2, v3);
            }
        }
    }
}

// ---------------- SIMT GEMM (small-N path): C = A*B^T + bias (+act) ----------------
// act: 0 none, 1 relu, 2 tanh*scale. 128x64 tile, BK=16, static double-buffered smem.
__global__ __launch_bounds__(256, 2)
void gemm_nt(const float* __restrict__ A, const float* __restrict__ Bw,
             const float* __restrict__ bias, const float* __restrict__ res,
             float* __restrict__ C, int M, int N, int K, int act, float scale)
{
    __shared__ float As[2][16][136];
    __shared__ float Bs[2][16][72];
    int bm = blockIdx.y * 128, bn = blockIdx.x * 64;
    int tid = threadIdx.x;
    int tx = tid & 15, ty = tid >> 4;

    int am = tid >> 1, ak = (tid & 1) * 8;
    int bnr = tid >> 2, bk = (tid & 3) * 4;
    int gmA = bm + am;  bool va = (gmA < M);
    int gnB = bn + bnr; bool vb = (gnB < N);
    const float* Ap = A  + (size_t)(va ? gmA : 0) * K + ak;
    const float* Bp = Bw + (size_t)(vb ? gnB : 0) * K + bk;

    const float4 fz = make_float4(0.f, 0.f, 0.f, 0.f);
    float4 a0 = va ? *(const float4*)(Ap)     : fz;
    float4 a1 = va ? *(const float4*)(Ap + 4) : fz;
    float4 b0 = vb ? *(const float4*)(Bp)     : fz;

    float acc[8][4];
    #pragma unroll
    for (int i = 0; i < 8; i++)
        #pragma unroll
        for (int j = 0; j < 4; j++) acc[i][j] = 0.f;

    As[0][ak+0][am] = a0.x; As[0][ak+1][am] = a0.y; As[0][ak+2][am] = a0.z; As[0][ak+3][am] = a0.w;
    As[0][ak+4][am] = a1.x; As[0][ak+5][am] = a1.y; As[0][ak+6][am] = a1.z; As[0][ak+7][am] = a1.w;
    Bs[0][bk+0][bnr] = b0.x; Bs[0][bk+1][bnr] = b0.y; Bs[0][bk+2][bnr] = b0.z; Bs[0][bk+3][bnr] = b0.w;
    __syncthreads();

    int nt = K >> 4;
    for (int t = 0; t < nt; t++) {
        int buf = t & 1;
        bool more = (t + 1 < nt);
        if (more) {
            const float* Ap2 = Ap + (t + 1) * 16;
            const float* Bp2 = Bp + (t + 1) * 16;
            a0 = va ? *(const float4*)(Ap2)     : fz;
            a1 = va ? *(const float4*)(Ap2 + 4) : fz;
            b0 = vb ? *(const float4*)(Bp2)     : fz;
        }
        #pragma unroll
        for (int kk = 0; kk < 16; kk++) {
            float4 x0 = *(const float4*)&As[buf][kk][ty*8];
            float4 x1 = *(const float4*)&As[buf][kk][ty*8 + 4];
            float4 y0 = *(const float4*)&Bs[buf][kk][tx*4];
            float av[8] = {x0.x,x0.y,x0.z,x0.w,x1.x,x1.y,x1.z,x1.w};
            float bv[4] = {y0.x,y0.y,y0.z,y0.w};
            #pragma unroll
            for (int i = 0; i < 8; i++)
                #pragma unroll
                for (int j = 0; j < 4; j++)
                    acc[i][j] += av[i] * bv[j];
        }
        if (more) {
            int nb = buf ^ 1;
            As[nb][ak+0][am] = a0.x; As[nb][ak+1][am] = a0.y; As[nb][ak+2][am] = a0.z; As[nb][ak+3][am] = a0.w;
            As[nb][ak+4][am] = a1.x; As[nb][ak+5][am] = a1.y; As[nb][ak+6][am] = a1.z; As[nb][ak+7][am] = a1.w;
            Bs[nb][bk+0][bnr] = b0.x; Bs[nb][bk+1][bnr] = b0.y; Bs[nb][bk+2][bnr] = b0.z; Bs[nb][bk+3][bnr] = b0.w;
        }
        __syncthreads();
    }

    #pragma unroll
    for (int i = 0; i < 8; i++) {
        int gm = bm + ty*8 + i;
        if (gm >= M) continue;
        #pragma unroll
        for (int j = 0; j < 4; j++) {
            int gn = bn + tx*4 + j;
            if (gn >= N) continue;
            float v = acc[i][j] + bias[gn];
            if (act == 1) v = fmaxf(v, 0.f);
            else if (act == 2) v = tanhf(v) * scale;
            if (res) v += res[(size_t)gm * N + gn];
            C[(size_t)gm * N + gn] = v;
        }
    }
}

// ---------------- Flash-style multi-head self-attention ----------------
#define ATT_SMEM_BYTES (23360*4)

__global__ __launch_bounds__(256, 2)
void attn_kernel(const float* __restrict__ qkv, float* __restrict__ out)
{
    extern __shared__ float sm[];
    float* Qs  = sm;            // [d][q] : 32 x 68
    float* Ks  = sm + 2176;     // [d][k] : 32 x 132
    float* Ps  = sm + 6400;     // [k][q] swizzled, stride 100
    float* Lsm = sm + 19200;    // [64]
    float* Vs  = sm + 19264;    // [k][d] swizzled: col slot ((d>>2)+k)&7

    int b = blockIdx.z, h = blockIdx.y;
    int q0 = blockIdx.x * 64;
    int tid = threadIdx.x;
    int tx = tid & 31, ty = tid >> 5;
    const float SCALE = 0.17677669529663687f;
    const float4 fz = make_float4(0,0,0,0);

    {
        int q = tid >> 2, dg = tid & 3;
        int gq = q0 + q;
        const float* src = qkv + (size_t)(b*NQ + (gq < NQ ? gq : 0))*768 + h*32 + dg*8;
        float4 x0 = fz, x1 = fz;
        if (gq < NQ) { x0 = *(const float4*)src; x1 = *(const float4*)(src + 4); }
        int d = dg * 8;
        Qs[(d+0)*68 + q] = x0.x; Qs[(d+1)*68 + q] = x0.y;
        Qs[(d+2)*68 + q] = x0.z; Qs[(d+3)*68 + q] = x0.w;
        Qs[(d+4)*68 + q] = x1.x; Qs[(d+5)*68 + q] = x1.y;
        Qs[(d+6)*68 + q] = x1.z; Qs[(d+7)*68 + q] = x1.w;
    }

    float o[8][4];
    float m[8], l[8];
    #pragma unroll
    for (int i = 0; i < 8; i++) {
        m[i] = -1e30f; l[i] = 0.f;
        #pragma unroll
        for (int j = 0; j < 4; j++) o[i][j] = 0.f;
    }

    int kg = tx >> 3, dgi = tx & 7;

    for (int c = 0; c < 8; c++) {
        int kc0 = c * 128;

        {
            int k = tid >> 1, dg = tid & 1;
            int kglob = kc0 + k;
            const float* src = qkv + (size_t)(b*NQ + (kglob < NQ ? kglob : 0))*768 + 256 + h*32 + dg*16;
            float4 x0 = fz, x1 = fz, x2 = fz, x3 = fz;
            if (kglob < NQ) {
                x0 = *(const float4*)(src);      x1 = *(const float4*)(src + 4);
                x2 = *(const float4*)(src + 8);  x3 = *(const float4*)(src + 12);
            }
            int d = dg * 16;
            Ks[(d+ 0)*132 + k] = x0.x; Ks[(d+ 1)*132 + k] = x0.y;
            Ks[(d+ 2)*132 + k] = x0.z; Ks[(d+ 3)*132 + k] = x0.w;
            Ks[(d+ 4)*132 + k] = x1.x; Ks[(d+ 5)*132 + k] = x1.y;
            Ks[(d+ 6)*132 + k] = x1.z; Ks[(d+ 7)*132 + k] = x1.w;
            Ks[(d+ 8)*132 + k] = x2.x; Ks[(d+ 9)*132 + k] = x2.y;
            Ks[(d+10)*132 + k] = x2.z; Ks[(d+11)*132 + k] = x2.w;
            Ks[(d+12)*132 + k] = x3.x; Ks[(d+13)*132 + k] = x3.y;
            Ks[(d+14)*132 + k] = x3.z; Ks[(d+15)*132 + k] = x3.w;
        }
        {
            int k = tid >> 1, dv = (tid & 1) * 16;
            int kglob = kc0 + k;
            const float* src = qkv + (size_t)(b*NQ + (kglob < NQ ? kglob : 0))*768 + 512 + h*32 + dv;
            float4 v0 = fz, v1 = fz, v2 = fz, v3 = fz;
            if (kglob < NQ) {
                v0 = *(const float4*)(src);      v1 = *(const float4*)(src + 4);
                v2 = *(const float4*)(src + 8);  v3 = *(const float4*)(src + 12);
            }
            int dq = dv >> 2;
            *(float4*)(Vs + k*32 + (((dq + 0) + k) & 7)*4) = v0;
            *(float4*)(Vs + k*32 + (((dq + 1) + k) & 7)*4) = v1;
            *(float4*)(Vs + k*32 + (((dq + 2) + k) & 7)*4) = v2;
            *(float4*)(Vs + k*32 + (((dq + 3) + k) & 7)*4) = v3;
        }
        __syncthreads();

        float acc[8][4];
        #pragma unroll
        for (int i = 0; i < 8; i++)
            #pragma unroll
            for (int j = 0; j < 4; j++) acc[i][j] = 0.f;

        #pragma unroll 8
        for (int d = 0; d < 32; d++) {
            const float4* Q4 = (const float4*)(Qs + d*68);
            float4 qa = Q4[ty*2], qb = Q4[ty*2 + 1];
            float4 kv = ((const float4*)(Ks + d*132))[tx];
            float qq[8] = {qa.x,qa.y,qa.z,qa.w,qb.x,qb.y,qb.z,qb.w};
            #pragma unroll
            for (int i = 0; i < 8; i++) {
                acc[i][0] += qq[i] * kv.x;
                acc[i][1] += qq[i] * kv.y;
                acc[i][2] += qq[i] * kv.z;
                acc[i][3] += qq[i] * kv.w;
            }
        }

        #pragma unroll
        for (int j = 0; j < 4; j++) {
            bool vk = (kc0 + tx*4 + j) < NQ;
            #pragma unroll
            for (int i = 0; i < 8; i++)
                acc[i][j] = vk ? acc[i][j]*SCALE : -1e30f;
        }

        #pragma unroll
        for (int i = 0; i < 8; i++) {
            float rm = fmaxf(fmaxf(acc[i][0], acc[i][1]), fmaxf(acc[i][2], acc[i][3]));
            #pragma unroll
            for (int off = 16; off; off >>= 1) rm = fmaxf(rm, __shfl_xor_sync(0xffffffffu, rm, off));
            float mn = fmaxf(m[i], rm);
            float alpha = __expf(m[i] - mn);
            m[i] = mn;
            float ls = 0.f;
            #pragma unroll
            for (int j = 0; j < 4; j++) {
                float p = __expf(acc[i][j] - mn);
                acc[i][j] = p;
                ls += p;
            }
            #pragma unroll
            for (int off = 16; off; off >>= 1) ls += __shfl_xor_sync(0xffffffffu, ls, off);
            l[i] = l[i]*alpha + ls;
            #pragma unroll
            for (int j = 0; j < 4; j++) o[i][j] *= alpha;
        }

        {
            int sw = (tx & 7) * 4;
            #pragma unroll
            for (int j = 0; j < 4; j++) {
                float* dst = Ps + (tx*4 + j)*100 + sw + ty*8;
                *(float4*)(dst)     = make_float4(acc[0][j], acc[1][j], acc[2][j], acc[3][j]);
                *(float4*)(dst + 4) = make_float4(acc[4][j], acc[5][j], acc[6][j], acc[7][j]);
            }
        }
        __syncthreads();

        {
            #pragma unroll 8
            for (int i2 = 0; i2 < 32; i2++) {
                int k = 4*i2 + kg;
                const float* prow = Ps + k*100 + (i2 & 7)*4;
                float4 pa = *(const float4*)(prow + ty*8);
                float4 pb = *(const float4*)(prow + ty*8 + 4);
                float4 v = *(const float4*)(Vs + k*32 + ((dgi + k) & 7)*4);
                float pv[8] = {pa.x,pa.y,pa.z,pa.w,pb.x,pb.y,pb.z,pb.w};
                #pragma unroll
                for (int i = 0; i < 8; i++) {
                    o[i][0] += pv[i] * v.x;
                    o[i][1] += pv[i] * v.y;
                    o[i][2] += pv[i] * v.z;
                    o[i][3] += pv[i] * v.w;
                }
            }
        }
        __syncthreads();
    }

    float* red = Ps;
    #pragma unroll
    for (int i = 0; i < 8; i++) {
        float* dst = red + kg*2048 + (ty*8 + i)*32 + dgi*4;
        *(float4*)dst = make_float4(o[i][0], o[i][1], o[i][2], o[i][3]);
    }
    if (tx == 0) {
        #pragma unroll
        for (int i = 0; i < 8; i++) Lsm[ty*8 + i] = l[i];
    }
    __syncthreads();

    {
        int q = tid >> 2, dgrp = tid & 3;
        int gq = q0 + q;
        if (gq < NQ) {
            int d = dgrp * 8;
            float s0 = 0, s1 = 0, s2 = 0, s3 = 0, s4 = 0, s5 = 0, s6 = 0, s7 = 0;
            #pragma unroll
            for (int g2 = 0; g2 < 4; g2++) {
                const float* src = red + g2*2048 + q*32 + d;
                float4 u = *(const float4*)(src);
                float4 w = *(const float4*)(src + 4);
                s0 += u.x; s1 += u.y; s2 += u.z; s3 += u.w;
                s4 += w.x; s5 += w.y; s6 += w.z; s7 += w.w;
            }
            float linv = 1.f / Lsm[q];
            float* dst = out + (size_t)(b*NQ + gq)*DD + h*32 + d;
            *(float4*)(dst)     = make_float4(s0*linv, s1*linv, s2*linv, s3*linv);
            *(float4*)(dst + 4) = make_float4(s4*linv, s5*linv, s6*linv, s7*linv);
        }
    }
}

// ---------------- BEV bilinear sampling + inline weight softmax + fuse ----------------
__global__ void sample_kernel(const float* __restrict__ mem, const float* __restrict__ ref,
                              const float* __restrict__ off, const float* __restrict__ wt,
                              float* __restrict__ out)
{
    int idx = blockIdx.x * 256 + threadIdx.x;
    if (idx >= M_ROWS * DD) return;
    int c = idx & 31;
    int h = (idx >> 5) & 7;
    int row = idx >> 8;
    int b = row / NQ;

    float rx = ref[row*2 + 0], ry = ref[row*2 + 1];
    const float* offr = off + (size_t)row*64 + h*8;
    const float* wtr  = wt  + (size_t)row*32 + h*4;
    const float* memb = mem + (size_t)b * (BEV*BEV) * DD + h*HD + c;

    float w0 = wtr[0], w1 = wtr[1], w2 = wtr[2], w3 = wtr[3];
    float wm = fmaxf(fmaxf(w0, w1), fmaxf(w2, w3));
    float e0 = __expf(w0 - wm), e1 = __expf(w1 - wm), e2 = __expf(w2 - wm), e3 = __expf(w3 - wm);
    float winv = 1.f / (e0 + e1 + e2 + e3);
    float wsm[4] = {e0*winv, e1*winv, e2*winv, e3*winv};

    float acc = 0.f;
    #pragma unroll
    for (int p = 0; p < PP; p++) {
        float gx = (rx + offr[p*2 + 0]) * (float)BEV - 0.5f;
        float gy = (ry + offr[p*2 + 1]) * (float)BEV - 0.5f;
        float x0f = floorf(gx), y0f = floorf(gy);
        int x0 = (int)x0f, y0 = (int)y0f;
        float wx1 = gx - x0f, wy1 = gy - y0f;
        float wx0 = 1.f - wx1, wy0 = 1.f - wy1;
        float v = 0.f;
        if ((unsigned)x0     < BEV && (unsigned)y0     < BEV) v += wx0*wy0 * memb[(size_t)(y0*BEV + x0    )*DD];
        if ((unsigned)(x0+1) < BEV && (unsigned)y0     < BEV) v += wx1*wy0 * memb[(size_t)(y0*BEV + x0 + 1)*DD];
        if ((unsigned)x0     < BEV && (unsigned)(y0+1) < BEV) v += wx0*wy1 * memb[(size_t)((y0+1)*BEV + x0    )*DD];
        if ((unsigned)(x0+1) < BEV && (unsigned)(y0+1) < BEV) v += wx1*wy1 * memb[(size_t)((y0+1)*BEV + x0 + 1)*DD];
        acc += wsm[p] * v;
    }
    out[idx] = acc;
}

// ---------------- launch ----------------
extern "C" void kernel_launch(void* const* d_in, const int* in_sizes, int n_in,
                              void* d_out, int out_size)
{
    const float* query   = (const float*)d_in[0];
    const float* memory  = (const float*)d_in[1];
    const float* refpts  = (const float*)d_in[2];
    const float* qpos    = (const float*)d_in[3];
    const float* in_w    = (const float*)d_in[4];
    const float* in_b    = (const float*)d_in[5];
    const float* out_w   = (const float*)d_in[6];
    const float* out_b   = (const float*)d_in[7];
    const float* off_w   = (const float*)d_in[8];
    const float* off_b   = (const float*)d_in[9];
    const float* wt_w    = (const float*)d_in[10];
    const float* wt_b    = (const float*)d_in[11];
    const float* co_w    = (const float*)d_in[12];
    const float* co_b    = (const float*)d_in[13];
    const float* f_w1    = (const float*)d_in[14];
    const float* f_b1    = (const float*)d_in[15];
    const float* f_w2    = (const float*)d_in[16];
    const float* f_b2    = (const float*)d_in[17];
    const float* n1s     = (const float*)d_in[18];
    const float* n1b     = (const float*)d_in[19];
    const float* n2s     = (const float*)d_in[20];
    const float* n2b     = (const float*)d_in[21];
    const float* n3s     = (const float*)d_in[22];
    const float* n3b     = (const float*)d_in[23];

    float* base = nullptr;
    cudaGetSymbolAddress((void**)&base, g_scratch);
    float* qin  = base + OFF_QIN;
    float* qkv  = base + OFF_QKV;
    float* attn = base + OFF_ATTN;
    float* q1   = base + OFF_Q1;
    float* q2   = base + OFF_Q2;
    float* off  = base + OFF_OFFS;
    float* wt   = base + OFF_WT;
    float* fus  = base + OFF_FUS;
    float* qu2  = base + OFF_QU2;
    float* q3   = base + OFF_Q3;
    float* h1   = base + OFF_H1;

    cudaFuncSetAttribute(attn_kernel, cudaFuncAttributeMaxDynamicSharedMemorySize, ATT_SMEM_BYTES);

    const int GY = (M_ROWS + 127) / 128;   // 57

    // 1) q_in = LN(query + pos; n1)
    ln_kernel<<<M_ROWS, 256>>>(query, qpos, n1s, n1b, qin);
    // 2) qkv = q_in @ in_w^T + in_b  (tensor core)
    gemm_tc<<<dim3(12, GY), 256>>>(qin, in_w, in_b, nullptr, qkv, M_ROWS, 768, 256, 0);
    // 3) self-attention (flash)
    attn_kernel<<<dim3((NQ + 63) / 64, HH, BB), 256, ATT_SMEM_BYTES>>>(qkv, attn);
    // 4) query1 = query + attn @ out_w^T + out_b  (tensor core)
    gemm_tc<<<dim3(4, GY), 256>>>(attn, out_w, out_b, query, q1, M_ROWS, 256, 256, 0);
    // 5) q2 = LN(query1 + pos; n2)
    ln_kernel<<<M_ROWS, 256>>>(q1, qpos, n2s, n2b, q2);
    // 6) offsets = tanh(q2 @ off_w^T + off_b) * RADIUS  (SIMT, N=64)
    gemm_nt<<<dim3(1, GY), 256>>>(q2, off_w, off_b, nullptr, off, M_ROWS, 64, 256, 2, 0.2f);
    // 7) raw weights  (SIMT, N=32)
    gemm_nt<<<dim3(1, GY), 256>>>(q2, wt_w, wt_b, nullptr, wt, M_ROWS, 32, 256, 0, 0.f);
    // 8) bilinear sample + softmax + fuse
    sample_kernel<<<(M_ROWS * DD + 255) / 256, 256>>>(memory, refpts, off, wt, fus);
    // 9) query2 = query1 + fused @ co_w^T + co_b  (tensor core)
    gemm_tc<<<dim3(4, GY), 256>>>(fus, co_w, co_b, q1, qu2, M_ROWS, 256, 256, 0);
    // 10) q3 = LN(query2; n3)
    ln_kernel<<<M_ROWS, 256>>>(qu2, nullptr, n3s, n3b, q3);
    // 11) h1 = relu(q3 @ f_w1^T + f_b1)  (tensor core)
    gemm_tc<<<dim3(8, GY), 256>>>(q3, f_w1, f_b1, nullptr, h1, M_ROWS, 512, 256, 1);
    // 12) out = query2 + h1 @ f_w2^T + f_b2  (tensor core, K=512)
    gemm_tc<<<dim3(4, GY), 256>>>(h1, f_w2, f_b2, qu2, (float*)d_out, M_ROWS, 256, 512, 0);
}